// round 8
// baseline (speedup 1.0000x reference)
#include <cuda_runtime.h>
#include <cstdint>

#define NE     1024
#define DDIM   64
#define HW     4096
#define NPIX   131072
#define QELEMS (NPIX * DDIM)
#define TILE   64
#define NTILES 8            // per half (512 codes / 64)
#define HSLAB  16
#define SLAB   32

// ---------------- device scratch ----------------
__device__ unsigned g_qe[NE * 16];            // int8 codes, 16 u32/code
__device__ float2   g_seh[NE];                // (se, hn)
__device__ float    g_codeT[NE * DDIM];       // fp32 codebook [code][dim]
__device__ float    g_hn[NE];
__device__ unsigned g_neB, g_ndeB;            // bits of max ||e||, max ||delta_e||
__device__ float    g_fc[(size_t)NPIX * DDIM];     // contiguous fp32 pixel vectors
__device__ float2   g_slab[(size_t)NPIX * SLAB];   // per-pixel: [half0 16 | half1 16]
__device__ int      g_cntP[2 * NPIX];
__device__ float    g_T[2 * NPIX];
__device__ int      g_widx[NPIX];
__device__ float    g_partial[512];

// ---------------- helpers ----------------
__device__ __forceinline__ unsigned smem_u32(const void* p) {
    unsigned a;
    asm("{ .reg .u64 t; cvta.to.shared.u64 t, %1; cvt.u32.u64 %0, t; }" : "=r"(a) : "l"(p));
    return a;
}
__device__ __forceinline__ void cpasync16(unsigned s, const void* g) {
    asm volatile("cp.async.cg.shared.global [%0], [%1], 16;" :: "r"(s), "l"(g));
}
__device__ __forceinline__ void cpasync8(unsigned s, const void* g) {
    asm volatile("cp.async.ca.shared.global [%0], [%1], 8;" :: "r"(s), "l"(g));
}
__device__ __forceinline__ void cpacommit() { asm volatile("cp.async.commit_group;"); }
template <int N> __device__ __forceinline__ void cpawait() {
    asm volatile("cp.async.wait_group %0;" :: "n"(N));
}
__device__ __forceinline__ void barh(int h) {   // per-half named barrier (64 threads)
    asm volatile("bar.sync %0, 64;" :: "r"(h + 1) : "memory");
}
__device__ __forceinline__ int q8(float v, float inv) {
    int q = (int)rintf(v * inv);
    return q < -127 ? -127 : (q > 127 ? 127 : q);
}
__device__ __forceinline__ unsigned pack4(int a, int b, int c, int d) {
    return (unsigned)(a & 0xFF) | ((unsigned)(b & 0xFF) << 8)
         | ((unsigned)(c & 0xFF) << 16) | ((unsigned)(d & 0xFF) << 24);
}
// exact int->float for |v| < 2^22 (IADD+FADD instead of I2F)
__device__ __forceinline__ float i2f_fast(int v) {
    return __int_as_float(v + 0x4B400000) - 12582912.0f;
}
// branchless candidate emission (predicated store, clamp to half-slab)
__device__ __forceinline__ void emit(float v, float t, int& cnt,
                                     unsigned long long slab, unsigned jbits) {
    asm volatile(
        "{\n\t"
        ".reg .pred p;\n\t"
        ".reg .s32 ci;\n\t"
        ".reg .s64 ad;\n\t"
        "setp.ge.f32 p, %1, %2;\n\t"
        "min.s32 ci, %0, 15;\n\t"
        "mad.wide.s32 ad, ci, 8, %3;\n\t"
        "@p st.global.v2.b32 [ad], {%4, %5};\n\t"
        "@p add.s32 %0, %0, 1;\n\t"
        "}\n"
        : "+r"(cnt)
        : "f"(v), "f"(t), "l"((long long)slab), "r"(__float_as_uint(v)), "r"(jbits));
}

// ---------------------------------------------------------------------------
// packB: embed [DDIM, NE] -> int8 codes + (se,hn) + fp32 codebook + norm maxima
// ---------------------------------------------------------------------------
__global__ void packB(const float* __restrict__ embed) {
    int j = blockIdx.x * 256 + threadIdx.x;
    if (j >= NE) return;
    float e[DDIM];
    float m = 0.f, n2 = 0.f;
#pragma unroll
    for (int d = 0; d < DDIM; d++) {
        float v = embed[d * NE + j];
        e[d] = v;
        g_codeT[j * DDIM + d] = v;
        m = fmaxf(m, fabsf(v));
        n2 += v * v;
    }
    float hn = 0.5f * n2;
    g_hn[j] = hn;
    float se = (m > 0.f) ? m * (1.0f / 127.0f) : 1.0f;
    float inv = 1.0f / se;
    float d2 = 0.f;
    int q[DDIM];
#pragma unroll
    for (int d = 0; d < DDIM; d++) {
        q[d] = q8(e[d], inv);
        float r = e[d] - se * (float)q[d];
        d2 += r * r;
    }
#pragma unroll
    for (int k = 0; k < 16; k++)
        g_qe[j * 16 + k] = pack4(q[4 * k], q[4 * k + 1], q[4 * k + 2], q[4 * k + 3]);
    g_seh[j] = make_float2(se, hn);
    atomicMax(&g_neB, __float_as_uint(sqrtf(n2)));
    atomicMax(&g_ndeB, __float_as_uint(sqrtf(d2)));
}

// ---------------------------------------------------------------------------
// prep_pixel (two-pass, low register peak): quantize + optional fp32 copy
// ---------------------------------------------------------------------------
__device__ __forceinline__ void prep_pixel(const float* __restrict__ xp, int p,
                                           unsigned* F, float& sf, float& w2,
                                           float nem, float ndem, bool writefc) {
    float m = 0.f;
#pragma unroll 8
    for (int d = 0; d < DDIM; d++) m = fmaxf(m, fabsf(xp[d * HW]));
    sf = (m > 0.f) ? m * (1.0f / 127.0f) : 1.0f;
    const float inv = 1.0f / sf;
    float d2 = 0.f, n2 = 0.f;
    float4* fc = (float4*)(g_fc + (size_t)p * DDIM);
#pragma unroll
    for (int k = 0; k < 16; k++) {
        float f0 = xp[(4 * k + 0) * HW];     // L1-resident (second pass)
        float f1 = xp[(4 * k + 1) * HW];
        float f2 = xp[(4 * k + 2) * HW];
        float f3 = xp[(4 * k + 3) * HW];
        int q0 = q8(f0, inv), q1 = q8(f1, inv), q2 = q8(f2, inv), q3 = q8(f3, inv);
        F[k] = pack4(q0, q1, q2, q3);
        float h0 = sf * (float)q0, h1 = sf * (float)q1, h2 = sf * (float)q2, h3 = sf * (float)q3;
        float r0 = f0 - h0, r1 = f1 - h1, r2 = f2 - h2, r3 = f3 - h3;
        d2 += r0 * r0 + r1 * r1 + r2 * r2 + r3 * r3;
        n2 += h0 * h0 + h1 * h1 + h2 * h2 + h3 * h3;
        if (writefc) fc[k] = make_float4(f0, f1, f2, f3);
    }
    w2 = 2.0f * (1.02f * (sqrtf(d2) * nem + sqrtf(n2) * ndem) + 1e-3f);
}

// ---------------------------------------------------------------------------
// vq_pass: 128 threads/CTA; half h (2 warps) scans codes [512h, 512h+512)
// for 128 pixels (2/thread). Per-half double-buffered code tiles.
// ---------------------------------------------------------------------------
__global__ void __launch_bounds__(128, 7) vq_pass(const float* __restrict__ x) {
    __shared__ unsigned sQ[2][2][TILE * 16];   // [half][buf] : 16 KB
    __shared__ float2   sSeh[2][512];          // 8 KB

    const int t = threadIdx.x;
    const int h = t >> 6, u = t & 63;
    const int jb0 = h * 512;
    const int p0 = blockIdx.x * 128 + u;
    const int p1 = p0 + 64;
    const int b = p0 >> 12;
    const float* xbase = x + (size_t)b * DDIM * HW;

    // prefetch: this half's (se,hn) block + tile 0
    {
        unsigned ss = smem_u32(&sSeh[h][0]);
#pragma unroll
        for (int i = 0; i < 8; i++)
            cpasync8(ss + (u + 64 * i) * 8, &g_seh[jb0 + u + 64 * i]);
        unsigned sq = smem_u32(&sQ[h][0][0]) + u * 64;
        const char* src = (const char*)(g_qe + (jb0 + u) * 16);
#pragma unroll
        for (int k = 0; k < 4; k++) cpasync16(sq + k * 16, src + k * 16);
        cpacommit();
    }

    const float nem = __uint_as_float(g_neB);
    const float ndem = __uint_as_float(g_ndeB);

    unsigned FA[16], FB[16];
    float sfA, w2A, sfB, w2B;
    prep_pixel(xbase + (p0 & 4095), p0, FA, sfA, w2A, nem, ndem, h == 0);
    prep_pixel(xbase + (p1 & 4095), p1, FB, sfB, w2B, nem, ndem, h == 0);

    float tA = -1e30f, tB = -1e30f;
    int cA = 0, cB = 0;
    const unsigned long long slabA =
        (unsigned long long)(g_slab + (size_t)p0 * SLAB + h * HSLAB);
    const unsigned long long slabB =
        (unsigned long long)(g_slab + (size_t)p1 * SLAB + h * HSLAB);

#pragma unroll 1
    for (int tile = 0; tile < NTILES; tile++) {
        if (tile + 1 < NTILES) {
            unsigned sq = smem_u32(&sQ[h][(tile + 1) & 1][0]) + u * 64;
            const char* src = (const char*)(g_qe + (jb0 + (tile + 1) * TILE + u) * 16);
#pragma unroll
            for (int k = 0; k < 4; k++) cpasync16(sq + k * 16, src + k * 16);
            cpacommit();
            cpawait<1>();
        } else {
            cpawait<0>();
        }
        barh(h);   // tile data visible to all 64 threads of this half

        const int buf = tile & 1;
        const int jb = jb0 + tile * TILE;
#pragma unroll 2
        for (int c = 0; c < TILE; c++) {
            const int4* qq = (const int4*)&sQ[h][buf][c * 16];
            float2 sh = sSeh[h][tile * TILE + c];
            int a0 = 0, a1 = 0, a2 = 0, a3 = 0;
            int e0 = 0, e1 = 0, e2 = 0, e3 = 0;
#pragma unroll
            for (int k = 0; k < 4; k++) {
                int4 qv = qq[k];
                a0 = __dp4a(qv.x, (int)FA[4 * k + 0], a0);
                a1 = __dp4a(qv.y, (int)FA[4 * k + 1], a1);
                a2 = __dp4a(qv.z, (int)FA[4 * k + 2], a2);
                a3 = __dp4a(qv.w, (int)FA[4 * k + 3], a3);
                e0 = __dp4a(qv.x, (int)FB[4 * k + 0], e0);
                e1 = __dp4a(qv.y, (int)FB[4 * k + 1], e1);
                e2 = __dp4a(qv.z, (int)FB[4 * k + 2], e2);
                e3 = __dp4a(qv.w, (int)FB[4 * k + 3], e3);
            }
            float fA = i2f_fast((a0 + a1) + (a2 + a3));
            float fB = i2f_fast((e0 + e1) + (e2 + e3));
            float csA = sfA * sh.x, csB = sfB * sh.x;
            float vA = fmaf(fA, csA, -sh.y);
            float vB = fmaf(fB, csB, -sh.y);
            unsigned jbits = (unsigned)(jb + c);
            emit(vA, tA, cA, slabA, jbits);
            tA = fmaxf(tA, vA - w2A);
            emit(vB, tB, cB, slabB, jbits);
            tB = fmaxf(tB, vB - w2B);
        }
        barh(h);   // all done with this buffer before next prefetch overwrites
    }

    g_T[h * NPIX + p0] = tA;
    g_T[h * NPIX + p1] = tB;
    g_cntP[h * NPIX + p0] = cA;
    g_cntP[h * NPIX + p1] = cB;
}

// ---------------------------------------------------------------------------
// resolve: warp per pixel. Merge both halves' slabs; exact fp32 rescore
// (full scan on overflow). Lowest-index tie-break.
// ---------------------------------------------------------------------------
__global__ void __launch_bounds__(256) resolve() {
    const int lane = threadIdx.x & 31;
    const int p = (blockIdx.x * blockDim.x + threadIdx.x) >> 5;

    const int c0 = g_cntP[p], c1 = g_cntP[NPIX + p];
    const float T = fmaxf(g_T[p], g_T[NPIX + p]);
    const float2 fv = ((const float2*)(g_fc + (size_t)p * DDIM))[lane];

    float bests = -3e38f;
    int bestj = 0;

    if (c0 <= HSLAB && c1 <= HSLAB) {
        const int i = lane & 15;
        const int ch = (lane >> 4) ? c1 : c0;
        float2 ent = (i < ch) ? g_slab[(size_t)p * SLAB + lane]
                              : make_float2(-3e38f, 0.f);
        unsigned mask = __ballot_sync(0xFFFFFFFFu, ent.x >= T);
        while (mask) {
            int src = __ffs(mask) - 1;   // ascending lane -> ascending j
            mask &= mask - 1;
            int j = __shfl_sync(0xFFFFFFFFu, __float_as_int(ent.y), src);
            float2 cv = ((const float2*)(g_codeT + (size_t)j * DDIM))[lane];
            float s = fmaf(fv.x, cv.x, fv.y * cv.y);
#pragma unroll
            for (int o = 16; o; o >>= 1) s += __shfl_xor_sync(0xFFFFFFFFu, s, o);
            s -= g_hn[j];
            if (s > bests) { bests = s; bestj = j; }
        }
    } else {
        for (int j = 0; j < NE; j++) {
            float2 cv = ((const float2*)(g_codeT + (size_t)j * DDIM))[lane];
            float s = fmaf(fv.x, cv.x, fv.y * cv.y);
#pragma unroll
            for (int o = 16; o; o >>= 1) s += __shfl_xor_sync(0xFFFFFFFFu, s, o);
            s -= g_hn[j];
            if (s > bests) { bests = s; bestj = j; }
        }
    }
    if (lane == 0) g_widx[p] = bestj;
}

// ---------------------------------------------------------------------------
// final_gather: write quantized output + loss partials
// ---------------------------------------------------------------------------
__global__ void __launch_bounds__(256) final_gather(const float* __restrict__ x,
                                                    float* __restrict__ out) {
    __shared__ float sRed[8];
    const int t = threadIdx.x;
    const int p = blockIdx.x * 256 + t;
    const int b = p >> 12, hw = p & 4095;
    const int idx = g_widx[p];

    const float* xb = x + (size_t)b * DDIM * HW + hw;
    float* ob = out + (size_t)b * DDIM * HW + hw;
    const float4* cr = (const float4*)(g_codeT + (size_t)idx * DDIM);
    float loss = 0.f;
#pragma unroll
    for (int kk = 0; kk < 16; kk++) {
        float4 q = cr[kk];
        int d = 4 * kk;
        float r;
        ob[(d + 0) * HW] = q.x; r = q.x - xb[(d + 0) * HW]; loss += r * r;
        ob[(d + 1) * HW] = q.y; r = q.y - xb[(d + 1) * HW]; loss += r * r;
        ob[(d + 2) * HW] = q.z; r = q.z - xb[(d + 2) * HW]; loss += r * r;
        ob[(d + 3) * HW] = q.w; r = q.w - xb[(d + 3) * HW]; loss += r * r;
    }
#pragma unroll
    for (int o = 16; o; o >>= 1) loss += __shfl_xor_sync(0xFFFFFFFFu, loss, o);
    if ((t & 31) == 0) sRed[t >> 5] = loss;
    __syncthreads();
    if (t == 0) {
        float s = 0.f;
#pragma unroll
        for (int w = 0; w < 8; w++) s += sRed[w];
        g_partial[blockIdx.x] = s;
    }
}

__global__ void fin_kernel(float* __restrict__ out, int last) {
    __shared__ float sRed[16];
    int t = threadIdx.x;  // 512
    float v = g_partial[t];
#pragma unroll
    for (int o = 16; o; o >>= 1) v += __shfl_xor_sync(0xFFFFFFFFu, v, o);
    if ((t & 31) == 0) sRed[t >> 5] = v;
    __syncthreads();
    if (t == 0) {
        double s = 0.0;
#pragma unroll
        for (int w = 0; w < 16; w++) s += (double)sRed[w];
        out[last] = (float)(s / (double)QELEMS);
    }
}

// ---------------------------------------------------------------------------
extern "C" void kernel_launch(void* const* d_in, const int* in_sizes, int n_in,
                              void* d_out, int out_size) {
    const float* x = (const float*)d_in[0];
    const float* embed = (const float*)d_in[1];
    if (n_in >= 2 && in_sizes[0] == NE * DDIM && in_sizes[1] == QELEMS) {
        const float* tmp = x; x = embed; embed = tmp;
    }
    float* out = (float*)d_out;

    packB<<<4, 256>>>(embed);
    vq_pass<<<NPIX / 128, 128>>>(x);
    resolve<<<NPIX / 8, 256>>>();
    final_gather<<<NPIX / 256, 256>>>(x, out);
    fin_kernel<<<1, 512>>>(out, out_size - 1);
}

// round 9
// speedup vs baseline: 2.8144x; 2.8144x over previous
#include <cuda_runtime.h>
#include <cstdint>

#define NE     1024
#define DDIM   64
#define HW     4096
#define NPIX   131072
#define QELEMS (NPIX * DDIM)
#define TILE   128
#define NTILES 8
#define SLAB   32

// ---------------- device scratch ----------------
__device__ unsigned g_qe[NE * 16];            // int8 codes, 16 u32/code
__device__ float2   g_seh[NE];                // (se, hn)
__device__ float    g_codeT[NE * DDIM];       // fp32 codebook [code][dim]
__device__ float    g_hn[NE];
__device__ unsigned g_neB, g_ndeB;            // bits of max ||e||, max ||delta_e||
__device__ float    g_fc[(size_t)NPIX * DDIM];     // contiguous fp32 pixel vectors
__device__ float2   g_slab[(size_t)NPIX * SLAB];   // per-pixel candidates (v, j)
__device__ int      g_cntP[NPIX];
__device__ float    g_T[NPIX];
__device__ int      g_widx[NPIX];
__device__ float    g_partial[512];

// ---------------- helpers ----------------
__device__ __forceinline__ unsigned smem_u32(const void* p) {
    unsigned a;
    asm("{ .reg .u64 t; cvta.to.shared.u64 t, %1; cvt.u32.u64 %0, t; }" : "=r"(a) : "l"(p));
    return a;
}
__device__ __forceinline__ void cpasync16(unsigned s, const void* g) {
    asm volatile("cp.async.cg.shared.global [%0], [%1], 16;" :: "r"(s), "l"(g));
}
__device__ __forceinline__ void cpasync8(unsigned s, const void* g) {
    asm volatile("cp.async.ca.shared.global [%0], [%1], 8;" :: "r"(s), "l"(g));
}
__device__ __forceinline__ void cpacommit() { asm volatile("cp.async.commit_group;"); }
template <int N> __device__ __forceinline__ void cpawait() {
    asm volatile("cp.async.wait_group %0;" :: "n"(N));
}
__device__ __forceinline__ int q8(float v, float inv) {
    int q = (int)rintf(v * inv);
    return q < -127 ? -127 : (q > 127 ? 127 : q);
}
__device__ __forceinline__ unsigned pack4(int a, int b, int c, int d) {
    return (unsigned)(a & 0xFF) | ((unsigned)(b & 0xFF) << 8)
         | ((unsigned)(c & 0xFF) << 16) | ((unsigned)(d & 0xFF) << 24);
}
// exact int->float for |v| < 2^22 (IADD+FADD instead of I2F)
__device__ __forceinline__ float i2f_fast(int v) {
    return __int_as_float(v + 0x4B400000) - 12582912.0f;
}
// branchless candidate emission (predicated store, clamp to slab)
__device__ __forceinline__ void emit(float v, float t, int& cnt,
                                     unsigned long long slab, unsigned jbits) {
    asm volatile(
        "{\n\t"
        ".reg .pred p;\n\t"
        ".reg .s32 ci;\n\t"
        ".reg .s64 ad;\n\t"
        "setp.ge.f32 p, %1, %2;\n\t"
        "min.s32 ci, %0, 31;\n\t"
        "mad.wide.s32 ad, ci, 8, %3;\n\t"
        "@p st.global.v2.b32 [ad], {%4, %5};\n\t"
        "@p add.s32 %0, %0, 1;\n\t"
        "}\n"
        : "+r"(cnt)
        : "f"(v), "f"(t), "l"((long long)slab), "r"(__float_as_uint(v)), "r"(jbits));
}

// ---------------------------------------------------------------------------
// packB: embed [DDIM, NE] -> int8 codes + (se,hn) + fp32 codebook + norm maxima
// ---------------------------------------------------------------------------
__global__ void packB(const float* __restrict__ embed) {
    int j = blockIdx.x * 256 + threadIdx.x;
    if (j >= NE) return;
    float e[DDIM];
    float m = 0.f, n2 = 0.f;
#pragma unroll
    for (int d = 0; d < DDIM; d++) {
        float v = embed[d * NE + j];
        e[d] = v;
        g_codeT[j * DDIM + d] = v;
        m = fmaxf(m, fabsf(v));
        n2 += v * v;
    }
    float hn = 0.5f * n2;
    g_hn[j] = hn;
    float se = (m > 0.f) ? m * (1.0f / 127.0f) : 1.0f;
    float inv = 1.0f / se;
    float d2 = 0.f;
    int q[DDIM];
#pragma unroll
    for (int d = 0; d < DDIM; d++) {
        q[d] = q8(e[d], inv);
        float r = e[d] - se * (float)q[d];
        d2 += r * r;
    }
#pragma unroll
    for (int k = 0; k < 16; k++)
        g_qe[j * 16 + k] = pack4(q[4 * k], q[4 * k + 1], q[4 * k + 2], q[4 * k + 3]);
    g_seh[j] = make_float2(se, hn);
    atomicMax(&g_neB, __float_as_uint(sqrtf(n2)));
    atomicMax(&g_ndeB, __float_as_uint(sqrtf(d2)));
}

// ---------------------------------------------------------------------------
// vq_pass: 128 threads/CTA, 1 pixel/thread, all 1024 codes from smem tiles.
// 8 CTAs/SM resident -> 8 warps/SMSP. No register spills (~55 regs).
// ---------------------------------------------------------------------------
__global__ void __launch_bounds__(128, 8) vq_pass(const float* __restrict__ x) {
    __shared__ unsigned sQ[2][TILE * 16];   // 2 x 8 KB double buffer
    __shared__ float2   sSeh[NE];           // 8 KB (all codes)

    const int t = threadIdx.x;
    const int p = blockIdx.x * 128 + t;
    const int b = p >> 12;
    const float* xp = x + (size_t)b * DDIM * HW + (p & 4095);

    // stage all (se,hn) + tile 0
    {
        unsigned ss = smem_u32(&sSeh[0]);
#pragma unroll
        for (int i = 0; i < 8; i++)
            cpasync8(ss + (t + 128 * i) * 8, &g_seh[t + 128 * i]);
        unsigned sq = smem_u32(&sQ[0][0]) + t * 64;
        const char* src = (const char*)(g_qe + t * 16);
#pragma unroll
        for (int k = 0; k < 4; k++) cpasync16(sq + k * 16, src + k * 16);
        cpacommit();
    }

    const float nem = __uint_as_float(g_neB);
    const float ndem = __uint_as_float(g_ndeB);

    // ---- pixel prep (two-pass to keep register peak low) ----
    float m = 0.f;
#pragma unroll 8
    for (int d = 0; d < DDIM; d++) m = fmaxf(m, fabsf(xp[d * HW]));
    const float sf = (m > 0.f) ? m * (1.0f / 127.0f) : 1.0f;
    const float inv = 1.0f / sf;
    unsigned F[16];
    float d2 = 0.f, n2 = 0.f;
    {
        float4* fc = (float4*)(g_fc + (size_t)p * DDIM);
#pragma unroll
        for (int k = 0; k < 16; k++) {
            float f0 = xp[(4 * k + 0) * HW];   // L1-resident second pass
            float f1 = xp[(4 * k + 1) * HW];
            float f2 = xp[(4 * k + 2) * HW];
            float f3 = xp[(4 * k + 3) * HW];
            int q0 = q8(f0, inv), q1 = q8(f1, inv), q2 = q8(f2, inv), q3 = q8(f3, inv);
            F[k] = pack4(q0, q1, q2, q3);
            float h0 = sf * (float)q0, h1 = sf * (float)q1;
            float h2 = sf * (float)q2, h3 = sf * (float)q3;
            float r0 = f0 - h0, r1 = f1 - h1, r2 = f2 - h2, r3 = f3 - h3;
            d2 += r0 * r0 + r1 * r1 + r2 * r2 + r3 * r3;
            n2 += h0 * h0 + h1 * h1 + h2 * h2 + h3 * h3;
            fc[k] = make_float4(f0, f1, f2, f3);
        }
    }
    const float w2 = 2.0f * (1.02f * (sqrtf(d2) * nem + sqrtf(n2) * ndem) + 1e-3f);

    float th = -1e30f;     // running (max - w2)
    int cnt = 0;
    const unsigned long long slab = (unsigned long long)(g_slab + (size_t)p * SLAB);

#pragma unroll 1
    for (int tile = 0; tile < NTILES; tile++) {
        if (tile + 1 < NTILES) {
            unsigned sq = smem_u32(&sQ[(tile + 1) & 1][0]) + t * 64;
            const char* src = (const char*)(g_qe + ((tile + 1) * TILE + t) * 16);
#pragma unroll
            for (int k = 0; k < 4; k++) cpasync16(sq + k * 16, src + k * 16);
            cpacommit();
            cpawait<1>();
        } else {
            cpawait<0>();
        }
        __syncthreads();

        const int buf = tile & 1;
        const int jb = tile * TILE;
#pragma unroll 2
        for (int c = 0; c < TILE; c++) {
            const int4* qq = (const int4*)&sQ[buf][c * 16];
            float2 sh = sSeh[jb + c];
            int a0 = 0, a1 = 0, a2 = 0, a3 = 0;
#pragma unroll
            for (int k = 0; k < 4; k++) {
                int4 qv = qq[k];
                a0 = __dp4a(qv.x, (int)F[4 * k + 0], a0);
                a1 = __dp4a(qv.y, (int)F[4 * k + 1], a1);
                a2 = __dp4a(qv.z, (int)F[4 * k + 2], a2);
                a3 = __dp4a(qv.w, (int)F[4 * k + 3], a3);
            }
            float fa = i2f_fast((a0 + a1) + (a2 + a3));
            float v = fmaf(fa, sf * sh.x, -sh.y);
            emit(v, th, cnt, slab, (unsigned)(jb + c));
            th = fmaxf(th, v - w2);
        }
        __syncthreads();
    }

    g_T[p] = th;
    g_cntP[p] = cnt;
}

// ---------------------------------------------------------------------------
// resolve: warp per pixel. Exact fp32 rescore of survivors
// (full scan on slab overflow). Lowest-index tie-break.
// ---------------------------------------------------------------------------
__global__ void __launch_bounds__(256) resolve() {
    const int lane = threadIdx.x & 31;
    const int p = (blockIdx.x * blockDim.x + threadIdx.x) >> 5;

    const int cnt = g_cntP[p];
    const float T = g_T[p];
    const float2 fv = ((const float2*)(g_fc + (size_t)p * DDIM))[lane];

    float bests = -3e38f;
    int bestj = 0;

    if (cnt <= SLAB) {
        float2 ent = (lane < cnt) ? g_slab[(size_t)p * SLAB + lane]
                                  : make_float2(-3e38f, 0.f);
        unsigned mask = __ballot_sync(0xFFFFFFFFu, ent.x >= T);
        while (mask) {
            int src = __ffs(mask) - 1;   // ascending lane -> ascending j
            mask &= mask - 1;
            int j = __shfl_sync(0xFFFFFFFFu, __float_as_int(ent.y), src);
            float2 cv = ((const float2*)(g_codeT + (size_t)j * DDIM))[lane];
            float s = fmaf(fv.x, cv.x, fv.y * cv.y);
#pragma unroll
            for (int o = 16; o; o >>= 1) s += __shfl_xor_sync(0xFFFFFFFFu, s, o);
            s -= g_hn[j];
            if (s > bests) { bests = s; bestj = j; }
        }
    } else {
        for (int j = 0; j < NE; j++) {
            float2 cv = ((const float2*)(g_codeT + (size_t)j * DDIM))[lane];
            float s = fmaf(fv.x, cv.x, fv.y * cv.y);
#pragma unroll
            for (int o = 16; o; o >>= 1) s += __shfl_xor_sync(0xFFFFFFFFu, s, o);
            s -= g_hn[j];
            if (s > bests) { bests = s; bestj = j; }
        }
    }
    if (lane == 0) g_widx[p] = bestj;
}

// ---------------------------------------------------------------------------
// final_gather: write quantized output + loss partials
// ---------------------------------------------------------------------------
__global__ void __launch_bounds__(256) final_gather(const float* __restrict__ x,
                                                    float* __restrict__ out) {
    __shared__ float sRed[8];
    const int t = threadIdx.x;
    const int p = blockIdx.x * 256 + t;
    const int b = p >> 12, hw = p & 4095;
    const int idx = g_widx[p];

    const float* xb = x + (size_t)b * DDIM * HW + hw;
    float* ob = out + (size_t)b * DDIM * HW + hw;
    const float4* cr = (const float4*)(g_codeT + (size_t)idx * DDIM);
    float loss = 0.f;
#pragma unroll
    for (int kk = 0; kk < 16; kk++) {
        float4 q = cr[kk];
        int d = 4 * kk;
        float r;
        ob[(d + 0) * HW] = q.x; r = q.x - xb[(d + 0) * HW]; loss += r * r;
        ob[(d + 1) * HW] = q.y; r = q.y - xb[(d + 1) * HW]; loss += r * r;
        ob[(d + 2) * HW] = q.z; r = q.z - xb[(d + 2) * HW]; loss += r * r;
        ob[(d + 3) * HW] = q.w; r = q.w - xb[(d + 3) * HW]; loss += r * r;
    }
#pragma unroll
    for (int o = 16; o; o >>= 1) loss += __shfl_xor_sync(0xFFFFFFFFu, loss, o);
    if ((t & 31) == 0) sRed[t >> 5] = loss;
    __syncthreads();
    if (t == 0) {
        float s = 0.f;
#pragma unroll
        for (int w = 0; w < 8; w++) s += sRed[w];
        g_partial[blockIdx.x] = s;
    }
}

__global__ void fin_kernel(float* __restrict__ out, int last) {
    __shared__ float sRed[16];
    int t = threadIdx.x;  // 512
    float v = g_partial[t];
#pragma unroll
    for (int o = 16; o; o >>= 1) v += __shfl_xor_sync(0xFFFFFFFFu, v, o);
    if ((t & 31) == 0) sRed[t >> 5] = v;
    __syncthreads();
    if (t == 0) {
        double s = 0.0;
#pragma unroll
        for (int w = 0; w < 16; w++) s += (double)sRed[w];
        out[last] = (float)(s / (double)QELEMS);
    }
}

// ---------------------------------------------------------------------------
extern "C" void kernel_launch(void* const* d_in, const int* in_sizes, int n_in,
                              void* d_out, int out_size) {
    const float* x = (const float*)d_in[0];
    const float* embed = (const float*)d_in[1];
    if (n_in >= 2 && in_sizes[0] == NE * DDIM && in_sizes[1] == QELEMS) {
        const float* tmp = x; x = embed; embed = tmp;
    }
    float* out = (float*)d_out;

    packB<<<4, 256>>>(embed);
    vq_pass<<<NPIX / 128, 128>>>(x);
    resolve<<<NPIX / 8, 256>>>();
    final_gather<<<NPIX / 256, 256>>>(x, out);
    fin_kernel<<<1, 512>>>(out, out_size - 1);
}